// round 16
// baseline (speedup 1.0000x reference)
#include <cuda_runtime.h>
#include <cuda_fp16.h>

#define Nn   100000
#define Ne   3200000
#define NNZn 6400000
#define NF   16
#define SCAN_C 512
#define NBLK ((Nn + SCAN_C - 1) / SCAN_C)   // 196

// ---- scratch (device globals; no allocation allowed) ----
__device__ __align__(16) float  g_z1[Nn * NF];
__device__ __align__(16) float  g_z2[Nn * NF];
__device__ __align__(16) float  g_zT[Nn * NF];
__device__ __align__(16) float  g_z4[Nn * NF];
__device__ __align__(16) float  g_pmy[Nn * NF];
__device__ __align__(16) __half g_fbh[(size_t)Ne * NF];   // fp16 copy of feat_b (102MB)
__device__ float g_stats[32];   // [0:16) sum, [16:32) sumsq

// CSR build scratch
__device__ int  g_cnt_h[Nn];
__device__ int  g_cnt_p[Nn];
__device__ int  g_rp_h[Nn + 1];
__device__ int  g_rp_p[Nn + 1];
__device__ int  g_cur_h[Nn];
__device__ int  g_cur_p[Nn];
__device__ int  g_bsum_h[NBLK];
__device__ int  g_bsum_p[NBLK];
__device__ int  g_csr_src[Ne];
__device__ __align__(8) int2 g_csr_cv[NNZn];   // (col, val-bits)

__device__ __forceinline__ float2 h2f(unsigned u) {
    __half2 h = *reinterpret_cast<__half2*>(&u);
    return __half22float2(h);
}
__device__ __forceinline__ unsigned f2h(float a, float b) {
    __half2 h = __floats2half2_rn(a, b);
    return *reinterpret_cast<unsigned*>(&h);
}

// ---- zero kernels (split per path for stream overlap) ----
__global__ void zero_hop_kernel() {
    int tid = blockIdx.x * blockDim.x + threadIdx.x;
    int stride = gridDim.x * blockDim.x;
    for (int i = tid; i < Nn; i += stride) g_cnt_h[i] = 0;
    if (blockIdx.x == 0 && threadIdx.x < 32) g_stats[threadIdx.x] = 0.f;
}
__global__ void zero_pm_kernel() {
    int tid = blockIdx.x * blockDim.x + threadIdx.x;
    int stride = gridDim.x * blockDim.x;
    for (int i = tid; i < Nn; i += stride) g_cnt_p[i] = 0;
}

// ---- feat_b fp32 -> fp16 streaming conversion ----
__global__ void convert_fb(const float* __restrict__ fb) {
    int tid = blockIdx.x * blockDim.x + threadIdx.x;
    int stride = gridDim.x * blockDim.x;
    const int n4 = Ne * NF / 4;   // 12.8M float4 chunks
    const float4* in = (const float4*)fb;
    uint2* out = (uint2*)g_fbh;
    for (int i = tid; i < n4; i += stride) {
        float4 v = __ldg(in + i);
        uint2 o;
        o.x = f2h(v.x, v.y);
        o.y = f2h(v.z, v.w);
        out[i] = o;
    }
}

// ---- histogram, 4 items per thread (1 LDG.128 + 4 RED per 4 items) ----
__global__ void hist4_kernel(const int4* __restrict__ idx, int n4, int* __restrict__ cnt) {
    int i = blockIdx.x * blockDim.x + threadIdx.x;
    if (i >= n4) return;
    int4 v = __ldg(idx + i);
    atomicAdd(&cnt[v.x], 1);
    atomicAdd(&cnt[v.y], 1);
    atomicAdd(&cnt[v.z], 1);
    atomicAdd(&cnt[v.w], 1);
}

// ---- 2-level exclusive scan over Nn counts ----
__global__ void scan_reduce(const int* __restrict__ cnt, int* __restrict__ bsum) {
    __shared__ int s[SCAN_C];
    int t = threadIdx.x;
    int i = blockIdx.x * SCAN_C + t;
    s[t] = (i < Nn) ? cnt[i] : 0;
    __syncthreads();
    for (int off = SCAN_C / 2; off > 0; off >>= 1) {
        if (t < off) s[t] += s[t + off];
        __syncthreads();
    }
    if (t == 0) bsum[blockIdx.x] = s[0];
}

__global__ void scan_bsums(int* __restrict__ bsum) {   // NBLK <= 256
    __shared__ int s[256];
    int t = threadIdx.x;
    int v = (t < NBLK) ? bsum[t] : 0;
    s[t] = v;
    __syncthreads();
    for (int off = 1; off < 256; off <<= 1) {
        int x = (t >= off) ? s[t - off] : 0;
        __syncthreads();
        s[t] += x;
        __syncthreads();
    }
    if (t < NBLK) bsum[t] = s[t] - v;   // exclusive
}

__global__ void scan_final(const int* __restrict__ cnt, const int* __restrict__ bsum,
                           int* __restrict__ rp, int* __restrict__ cur, int total) {
    __shared__ int s[SCAN_C];
    int t = threadIdx.x;
    int i = blockIdx.x * SCAN_C + t;
    int v = (i < Nn) ? cnt[i] : 0;
    s[t] = v;
    __syncthreads();
    for (int off = 1; off < SCAN_C; off <<= 1) {
        int x = (t >= off) ? s[t - off] : 0;
        __syncthreads();
        s[t] += x;
        __syncthreads();
    }
    if (i < Nn) {
        int e = bsum[blockIdx.x] + s[t] - v;
        rp[i] = e;
        cur[i] = e;
    }
    if (i == 0) rp[Nn] = total;
}

// ---- scatter into CSR slots, 4 items per thread ----
__global__ void scat_hop4(const int4* __restrict__ src, const int4* __restrict__ dst) {
    int i = blockIdx.x * blockDim.x + threadIdx.x;
    if (i >= Ne / 4) return;
    int4 s = __ldg(src + i);
    int4 d = __ldg(dst + i);
    g_csr_src[atomicAdd(&g_cur_h[d.x], 1)] = s.x;
    g_csr_src[atomicAdd(&g_cur_h[d.y], 1)] = s.y;
    g_csr_src[atomicAdd(&g_cur_h[d.z], 1)] = s.z;
    g_csr_src[atomicAdd(&g_cur_h[d.w], 1)] = s.w;
}

__global__ void scat_pm4(const int4* __restrict__ rows, const int4* __restrict__ cols,
                         const float4* __restrict__ vals) {
    int i = blockIdx.x * blockDim.x + threadIdx.x;
    if (i >= NNZn / 4) return;
    int4 r = __ldg(rows + i);
    int4 c = __ldg(cols + i);
    float4 v = __ldg(vals + i);
    g_csr_cv[atomicAdd(&g_cur_p[r.x], 1)] = make_int2(c.x, __float_as_int(v.x));
    g_csr_cv[atomicAdd(&g_cur_p[r.y], 1)] = make_int2(c.y, __float_as_int(v.y));
    g_csr_cv[atomicAdd(&g_cur_p[r.z], 1)] = make_int2(c.z, __float_as_int(v.z));
    g_csr_cv[atomicAdd(&g_cur_p[r.w], 1)] = make_int2(c.w, __float_as_int(v.w));
}

// ---- hop: ONE thread per node. Per edge: 1 idx LDG + 4 LDG.128 (5 ops). ----
__global__ void hop_gather(const float* __restrict__ zin, float* __restrict__ zout) {
    int node = blockIdx.x * blockDim.x + threadIdx.x;
    if (node >= Nn) return;
    int e = __ldg(&g_rp_h[node]);
    int end = __ldg(&g_rp_h[node + 1]);
    float4 a0 = make_float4(0.f, 0.f, 0.f, 0.f);
    float4 a1 = a0, a2 = a0, a3 = a0;
    for (; e + 3 < end; e += 4) {
        int s[4];
#pragma unroll
        for (int k = 0; k < 4; k++) s[k] = __ldg(&g_csr_src[e + k]);
        float4 v[4][4];
#pragma unroll
        for (int k = 0; k < 4; k++) {
            const float4* p = (const float4*)(zin + (size_t)s[k] * NF);
            v[k][0] = __ldg(p + 0);
            v[k][1] = __ldg(p + 1);
            v[k][2] = __ldg(p + 2);
            v[k][3] = __ldg(p + 3);
        }
#pragma unroll
        for (int k = 0; k < 4; k++) {
            a0.x += v[k][0].x; a0.y += v[k][0].y; a0.z += v[k][0].z; a0.w += v[k][0].w;
            a1.x += v[k][1].x; a1.y += v[k][1].y; a1.z += v[k][1].z; a1.w += v[k][1].w;
            a2.x += v[k][2].x; a2.y += v[k][2].y; a2.z += v[k][2].z; a2.w += v[k][2].w;
            a3.x += v[k][3].x; a3.y += v[k][3].y; a3.z += v[k][3].z; a3.w += v[k][3].w;
        }
    }
    for (; e < end; e++) {
        int s = __ldg(&g_csr_src[e]);
        const float4* p = (const float4*)(zin + (size_t)s * NF);
        float4 v0 = __ldg(p + 0), v1 = __ldg(p + 1), v2 = __ldg(p + 2), v3 = __ldg(p + 3);
        a0.x += v0.x; a0.y += v0.y; a0.z += v0.z; a0.w += v0.w;
        a1.x += v1.x; a1.y += v1.y; a1.z += v1.z; a1.w += v1.w;
        a2.x += v2.x; a2.y += v2.y; a2.z += v2.z; a2.w += v2.w;
        a3.x += v3.x; a3.y += v3.y; a3.z += v3.z; a3.w += v3.w;
    }
    float4* o = (float4*)(zout + (size_t)node * NF);
    o[0] = a0; o[1] = a1; o[2] = a2; o[3] = a3;
}

// ---- pm: ONE thread per node over fp16 feat_b. Per nnz: 1 LDG.64 + 2 LDG.128 (3 ops). ----
__global__ void pm_gather_h() {
    int node = blockIdx.x * blockDim.x + threadIdx.x;
    if (node >= Nn) return;
    int e = __ldg(&g_rp_p[node]);
    int end = __ldg(&g_rp_p[node + 1]);
    const uint4* fb4 = (const uint4*)g_fbh;   // 16B = 8 halves; row = 2 uint4
    float acc[16];
#pragma unroll
    for (int j = 0; j < 16; j++) acc[j] = 0.f;
    for (; e + 3 < end; e += 4) {
        int2 cv[4];
#pragma unroll
        for (int k = 0; k < 4; k++) cv[k] = __ldg(&g_csr_cv[e + k]);
        uint4 u[4][2];
#pragma unroll
        for (int k = 0; k < 4; k++) {
            const uint4* p = fb4 + (size_t)cv[k].x * 2;
            u[k][0] = __ldg(p + 0);
            u[k][1] = __ldg(p + 1);
        }
#pragma unroll
        for (int k = 0; k < 4; k++) {
            float w = __int_as_float(cv[k].y);
            unsigned uu[8] = {u[k][0].x, u[k][0].y, u[k][0].z, u[k][0].w,
                              u[k][1].x, u[k][1].y, u[k][1].z, u[k][1].w};
#pragma unroll
            for (int h = 0; h < 8; h++) {
                float2 f = h2f(uu[h]);
                acc[h * 2 + 0] += f.x * w;
                acc[h * 2 + 1] += f.y * w;
            }
        }
    }
    for (; e < end; e++) {
        int2 cv = __ldg(&g_csr_cv[e]);
        const uint4* p = fb4 + (size_t)cv.x * 2;
        uint4 u0 = __ldg(p + 0), u1 = __ldg(p + 1);
        float w = __int_as_float(cv.y);
        unsigned uu[8] = {u0.x, u0.y, u0.z, u0.w, u1.x, u1.y, u1.z, u1.w};
#pragma unroll
        for (int h = 0; h < 8; h++) {
            float2 f = h2f(uu[h]);
            acc[h * 2 + 0] += f.x * w;
            acc[h * 2 + 1] += f.y * w;
        }
    }
    float4* o = (float4*)(g_pmy + (size_t)node * NF);
    o[0] = make_float4(acc[0], acc[1], acc[2], acc[3]);
    o[1] = make_float4(acc[4], acc[5], acc[6], acc[7]);
    o[2] = make_float4(acc[8], acc[9], acc[10], acc[11]);
    o[3] = make_float4(acc[12], acc[13], acc[14], acc[15]);
}

// ---- fused projection + relu + BN-stat accumulation ----
__global__ void final_kernel(const float* __restrict__ fa,
                             const float* __restrict__ deg,
                             const float* __restrict__ Wprev,
                             const float* __restrict__ bprev,
                             const float* __restrict__ Wdeg,
                             const float* __restrict__ bdeg,
                             const float* __restrict__ Wrad,
                             const float* __restrict__ brad,
                             const float* __restrict__ Wfuse,
                             const float* __restrict__ bfuse,
                             const float* __restrict__ z1,
                             const float* __restrict__ z2,
                             const float* __restrict__ z4,
                             const float* __restrict__ pmy,
                             float* __restrict__ out) {
    __shared__ float sW[1536];
    __shared__ float sB[16];
    __shared__ float sS[32];
    int t = threadIdx.x;
    for (int i = t; i < 256; i += blockDim.x) {
        sW[i] = Wprev[i];
        sW[256 + i] = Wdeg[i];
        sW[1280 + i] = Wfuse[i];
    }
    for (int i = t; i < 768; i += blockDim.x) sW[512 + i] = Wrad[i];
    if (t < 16)
        sB[t] = bprev[t] + bdeg[t] + brad[t] + brad[16 + t] + brad[32 + t] + bfuse[t];
    if (t < 32) sS[t] = 0.f;
    __syncthreads();

    int i = blockIdx.x * blockDim.x + t;
    bool valid = (i < Nn);

    float res[16];
#pragma unroll
    for (int j = 0; j < 16; j++) res[j] = valid ? sB[j] : 0.f;

    if (valid) {
        float in[16];
        const float4* p = (const float4*)(fa + (size_t)i * NF);
        *(float4*)(in + 0)  = p[0];
        *(float4*)(in + 4)  = p[1];
        *(float4*)(in + 8)  = p[2];
        *(float4*)(in + 12) = p[3];
        float dg = deg[i];
#pragma unroll
        for (int k = 0; k < 16; k++) {
            float xv = in[k];
            float xd = xv * dg;
#pragma unroll
            for (int j = 0; j < 16; j++)
                res[j] += xv * sW[k * 16 + j] + xd * sW[256 + k * 16 + j];
        }
        p = (const float4*)(z1 + (size_t)i * NF);
        *(float4*)(in + 0) = p[0]; *(float4*)(in + 4) = p[1];
        *(float4*)(in + 8) = p[2]; *(float4*)(in + 12) = p[3];
#pragma unroll
        for (int k = 0; k < 16; k++) {
            float xv = in[k];
#pragma unroll
            for (int j = 0; j < 16; j++) res[j] += xv * sW[512 + k * 16 + j];
        }
        p = (const float4*)(z2 + (size_t)i * NF);
        *(float4*)(in + 0) = p[0]; *(float4*)(in + 4) = p[1];
        *(float4*)(in + 8) = p[2]; *(float4*)(in + 12) = p[3];
#pragma unroll
        for (int k = 0; k < 16; k++) {
            float xv = in[k];
#pragma unroll
            for (int j = 0; j < 16; j++) res[j] += xv * sW[768 + k * 16 + j];
        }
        p = (const float4*)(z4 + (size_t)i * NF);
        *(float4*)(in + 0) = p[0]; *(float4*)(in + 4) = p[1];
        *(float4*)(in + 8) = p[2]; *(float4*)(in + 12) = p[3];
#pragma unroll
        for (int k = 0; k < 16; k++) {
            float xv = in[k];
#pragma unroll
            for (int j = 0; j < 16; j++) res[j] += xv * sW[1024 + k * 16 + j];
        }
        p = (const float4*)(pmy + (size_t)i * NF);
        *(float4*)(in + 0) = p[0]; *(float4*)(in + 4) = p[1];
        *(float4*)(in + 8) = p[2]; *(float4*)(in + 12) = p[3];
#pragma unroll
        for (int k = 0; k < 16; k++) {
            float xv = in[k];
#pragma unroll
            for (int j = 0; j < 16; j++) res[j] += xv * sW[1280 + k * 16 + j];
        }
#pragma unroll
        for (int j = 8; j < 16; j++) res[j] = fmaxf(res[j], 0.f);
        float4* o = (float4*)(out + (size_t)i * NF);
        o[0] = make_float4(res[0], res[1], res[2], res[3]);
        o[1] = make_float4(res[4], res[5], res[6], res[7]);
        o[2] = make_float4(res[8], res[9], res[10], res[11]);
        o[3] = make_float4(res[12], res[13], res[14], res[15]);
    }

    unsigned lane = t & 31u;
#pragma unroll
    for (int j = 0; j < 16; j++) {
        float s = res[j];
        float q = res[j] * res[j];
#pragma unroll
        for (int o = 16; o > 0; o >>= 1) {
            s += __shfl_xor_sync(0xffffffffu, s, o);
            q += __shfl_xor_sync(0xffffffffu, q, o);
        }
        if (lane == 0) {
            atomicAdd(&sS[j], s);
            atomicAdd(&sS[16 + j], q);
        }
    }
    __syncthreads();
    if (t < 32) atomicAdd(&g_stats[t], sS[t]);
}

// ---- apply batchnorm in place ----
__global__ void bn_kernel(float* __restrict__ out,
                          const float* __restrict__ gamma,
                          const float* __restrict__ beta) {
    __shared__ float sc[16], sh[16];
    if (threadIdx.x < 16) {
        int j = threadIdx.x;
        const float inv = 1.f / (float)Nn;
        float m = g_stats[j] * inv;
        float var = g_stats[16 + j] * inv - m * m;
        float s = rsqrtf(var + 1e-5f) * gamma[j];
        sc[j] = s;
        sh[j] = beta[j] - m * s;
    }
    __syncthreads();
    int tid = blockIdx.x * blockDim.x + threadIdx.x;
    int stride = gridDim.x * blockDim.x;
    const int n4 = Nn * 4;
    float4* o4 = (float4*)out;
    for (int i = tid; i < n4; i += stride) {
        int cb = (i & 3) * 4;
        float4 v = o4[i];
        v.x = v.x * sc[cb + 0] + sh[cb + 0];
        v.y = v.y * sc[cb + 1] + sh[cb + 1];
        v.z = v.z * sc[cb + 2] + sh[cb + 2];
        v.w = v.w * sc[cb + 3] + sh[cb + 3];
        o4[i] = v;
    }
}

extern "C" void kernel_launch(void* const* d_in, const int* in_sizes, int n_in,
                              void* d_out, int out_size) {
    const float* feat_a  = (const float*)d_in[0];
    const float* feat_b  = (const float*)d_in[1];
    const float* deg     = (const float*)d_in[2];
    const float* pm_vals = (const float*)d_in[3];
    const float* W_prev  = (const float*)d_in[4];
    const float* b_prev  = (const float*)d_in[5];
    const float* W_deg   = (const float*)d_in[6];
    const float* b_deg   = (const float*)d_in[7];
    const float* W_rad   = (const float*)d_in[8];
    const float* b_rad   = (const float*)d_in[9];
    const float* W_fuse  = (const float*)d_in[10];
    const float* b_fuse  = (const float*)d_in[11];
    const float* bn_g    = (const float*)d_in[12];
    const float* bn_b    = (const float*)d_in[13];
    const int*   src     = (const int*)d_in[14];
    const int*   dst     = (const int*)d_in[15];
    const int*   pm_rows = (const int*)d_in[16];
    const int*   pm_cols = (const int*)d_in[17];
    float* out = (float*)d_out;

    float *z1, *z2, *zT, *z4, *pmy;
    int *cnt_h, *cnt_p, *rp_h, *rp_p, *cur_h, *cur_p, *bs_h, *bs_p;
    cudaGetSymbolAddress((void**)&z1, g_z1);
    cudaGetSymbolAddress((void**)&z2, g_z2);
    cudaGetSymbolAddress((void**)&zT, g_zT);
    cudaGetSymbolAddress((void**)&z4, g_z4);
    cudaGetSymbolAddress((void**)&pmy, g_pmy);
    cudaGetSymbolAddress((void**)&cnt_h, g_cnt_h);
    cudaGetSymbolAddress((void**)&cnt_p, g_cnt_p);
    cudaGetSymbolAddress((void**)&rp_h, g_rp_h);
    cudaGetSymbolAddress((void**)&rp_p, g_rp_p);
    cudaGetSymbolAddress((void**)&cur_h, g_cur_h);
    cudaGetSymbolAddress((void**)&cur_p, g_cur_p);
    cudaGetSymbolAddress((void**)&bs_h, g_bsum_h);
    cudaGetSymbolAddress((void**)&bs_p, g_bsum_p);

    // Lazily-created side streams + events (host-side infra; device work is
    // identical every call). Fall back to single-stream if creation fails.
    static cudaStream_t s2 = 0, s3 = 0;
    static cudaEvent_t ev_fork = 0, ev_join = 0, ev_cv = 0;
    static int infra_ok = -1;
    if (infra_ok < 0) {
        infra_ok = 1;
        if (cudaStreamCreateWithFlags(&s2, cudaStreamNonBlocking) != cudaSuccess) infra_ok = 0;
        if (infra_ok && cudaStreamCreateWithFlags(&s3, cudaStreamNonBlocking) != cudaSuccess) infra_ok = 0;
        if (infra_ok && cudaEventCreateWithFlags(&ev_fork, cudaEventDisableTiming) != cudaSuccess) infra_ok = 0;
        if (infra_ok && cudaEventCreateWithFlags(&ev_join, cudaEventDisableTiming) != cudaSuccess) infra_ok = 0;
        if (infra_ok && cudaEventCreateWithFlags(&ev_cv, cudaEventDisableTiming) != cudaSuccess) infra_ok = 0;
    }
    cudaStream_t sp = infra_ok ? s2 : 0;   // pm-path stream
    cudaStream_t sc = infra_ok ? s3 : 0;   // feat_b-conversion stream

    const int TB = 256;
    const int TG = 128;                       // gather kernels: smaller blocks, better wave balance
    const int GN = (Nn + TG - 1) / TG;        // one thread per node

    if (infra_ok) {
        cudaEventRecord(ev_fork, 0);
        cudaStreamWaitEvent(sp, ev_fork, 0);
        cudaStreamWaitEvent(sc, ev_fork, 0);
    }

    // ---- conversion stream: feat_b -> fp16 (streaming) ----
    convert_fb<<<4096, TB, 0, sc>>>(feat_b);
    if (infra_ok) cudaEventRecord(ev_cv, sc);

    // ---- pm path (stream sp): CSR build, then fp16 gather ----
    zero_pm_kernel<<<256, TB, 0, sp>>>();
    hist4_kernel<<<(NNZn / 4 + TB - 1) / TB, TB, 0, sp>>>((const int4*)pm_rows, NNZn / 4, cnt_p);
    scan_reduce<<<NBLK, SCAN_C, 0, sp>>>(cnt_p, bs_p);
    scan_bsums<<<1, 256, 0, sp>>>(bs_p);
    scan_final<<<NBLK, SCAN_C, 0, sp>>>(cnt_p, bs_p, rp_p, cur_p, NNZn);
    scat_pm4<<<(NNZn / 4 + TB - 1) / TB, TB, 0, sp>>>(
        (const int4*)pm_rows, (const int4*)pm_cols, (const float4*)pm_vals);
    if (infra_ok) cudaStreamWaitEvent(sp, ev_cv, 0);   // need fbh ready
    pm_gather_h<<<GN, TG, 0, sp>>>();
    if (infra_ok) cudaEventRecord(ev_join, sp);

    // ---- hop path (default stream): CSR build + 4 gather hops ----
    zero_hop_kernel<<<256, TB>>>();
    hist4_kernel<<<(Ne / 4 + TB - 1) / TB, TB>>>((const int4*)dst, Ne / 4, cnt_h);
    scan_reduce<<<NBLK, SCAN_C>>>(cnt_h, bs_h);
    scan_bsums<<<1, 256>>>(bs_h);
    scan_final<<<NBLK, SCAN_C>>>(cnt_h, bs_h, rp_h, cur_h, Ne);
    scat_hop4<<<(Ne / 4 + TB - 1) / TB, TB>>>((const int4*)src, (const int4*)dst);
    hop_gather<<<GN, TG>>>(feat_a, z1);
    hop_gather<<<GN, TG>>>(z1, z2);
    hop_gather<<<GN, TG>>>(z2, zT);
    hop_gather<<<GN, TG>>>(zT, z4);

    // join pm path before final
    if (infra_ok) cudaStreamWaitEvent(0, ev_join, 0);

    final_kernel<<<(Nn + TB - 1) / TB, TB>>>(
        feat_a, deg, W_prev, b_prev, W_deg, b_deg, W_rad, b_rad,
        W_fuse, b_fuse, z1, z2, z4, pmy, out);

    bn_kernel<<<1024, TB>>>(out, bn_g, bn_b);
}

// round 17
// speedup vs baseline: 1.8589x; 1.8589x over previous
#include <cuda_runtime.h>

#define Nn   100000
#define Ne   3200000
#define NNZn 6400000
#define NF   16
#define SCAN_C 512
#define NBLK ((Nn + SCAN_C - 1) / SCAN_C)   // 196

// ---- scratch (device globals; no allocation allowed) ----
__device__ __align__(16) float g_z1[Nn * NF];
__device__ __align__(16) float g_z2[Nn * NF];
__device__ __align__(16) float g_zT[Nn * NF];
__device__ __align__(16) float g_z4[Nn * NF];
__device__ __align__(16) float g_pmy[Nn * NF];
__device__ float g_stats[32];   // [0:16) sum, [16:32) sumsq

// CSR build scratch
__device__ int  g_cnt_h[Nn];
__device__ int  g_cnt_p[Nn];
__device__ int  g_rp_h[Nn + 1];
__device__ int  g_rp_p[Nn + 1];
__device__ int  g_cur_h[Nn];
__device__ int  g_cur_p[Nn];
__device__ int  g_bsum_h[NBLK];
__device__ int  g_bsum_p[NBLK];
__device__ int  g_csr_src[Ne];
__device__ __align__(8) int2 g_csr_cv[NNZn];   // (col, val-bits)

// ---- zero kernels (split per path for stream overlap) ----
__global__ void zero_hop_kernel() {
    int tid = blockIdx.x * blockDim.x + threadIdx.x;
    int stride = gridDim.x * blockDim.x;
    for (int i = tid; i < Nn; i += stride) g_cnt_h[i] = 0;
    if (blockIdx.x == 0 && threadIdx.x < 32) g_stats[threadIdx.x] = 0.f;
}
__global__ void zero_pm_kernel() {
    int tid = blockIdx.x * blockDim.x + threadIdx.x;
    int stride = gridDim.x * blockDim.x;
    for (int i = tid; i < Nn; i += stride) g_cnt_p[i] = 0;
}

// ---- histogram, 4 items per thread (1 LDG.128 + 4 RED per 4 items) ----
__global__ void hist4_kernel(const int4* __restrict__ idx, int n4, int* __restrict__ cnt) {
    int i = blockIdx.x * blockDim.x + threadIdx.x;
    if (i >= n4) return;
    int4 v = __ldg(idx + i);
    atomicAdd(&cnt[v.x], 1);
    atomicAdd(&cnt[v.y], 1);
    atomicAdd(&cnt[v.z], 1);
    atomicAdd(&cnt[v.w], 1);
}

// ---- 2-level exclusive scan over Nn counts ----
__global__ void scan_reduce(const int* __restrict__ cnt, int* __restrict__ bsum) {
    __shared__ int s[SCAN_C];
    int t = threadIdx.x;
    int i = blockIdx.x * SCAN_C + t;
    s[t] = (i < Nn) ? cnt[i] : 0;
    __syncthreads();
    for (int off = SCAN_C / 2; off > 0; off >>= 1) {
        if (t < off) s[t] += s[t + off];
        __syncthreads();
    }
    if (t == 0) bsum[blockIdx.x] = s[0];
}

__global__ void scan_bsums(int* __restrict__ bsum) {   // NBLK <= 256
    __shared__ int s[256];
    int t = threadIdx.x;
    int v = (t < NBLK) ? bsum[t] : 0;
    s[t] = v;
    __syncthreads();
    for (int off = 1; off < 256; off <<= 1) {
        int x = (t >= off) ? s[t - off] : 0;
        __syncthreads();
        s[t] += x;
        __syncthreads();
    }
    if (t < NBLK) bsum[t] = s[t] - v;   // exclusive
}

__global__ void scan_final(const int* __restrict__ cnt, const int* __restrict__ bsum,
                           int* __restrict__ rp, int* __restrict__ cur, int total) {
    __shared__ int s[SCAN_C];
    int t = threadIdx.x;
    int i = blockIdx.x * SCAN_C + t;
    int v = (i < Nn) ? cnt[i] : 0;
    s[t] = v;
    __syncthreads();
    for (int off = 1; off < SCAN_C; off <<= 1) {
        int x = (t >= off) ? s[t - off] : 0;
        __syncthreads();
        s[t] += x;
        __syncthreads();
    }
    if (i < Nn) {
        int e = bsum[blockIdx.x] + s[t] - v;
        rp[i] = e;
        cur[i] = e;
    }
    if (i == 0) rp[Nn] = total;
}

// ---- scatter into CSR slots, 4 items per thread ----
__global__ void scat_hop4(const int4* __restrict__ src, const int4* __restrict__ dst) {
    int i = blockIdx.x * blockDim.x + threadIdx.x;
    if (i >= Ne / 4) return;
    int4 s = __ldg(src + i);
    int4 d = __ldg(dst + i);
    g_csr_src[atomicAdd(&g_cur_h[d.x], 1)] = s.x;
    g_csr_src[atomicAdd(&g_cur_h[d.y], 1)] = s.y;
    g_csr_src[atomicAdd(&g_cur_h[d.z], 1)] = s.z;
    g_csr_src[atomicAdd(&g_cur_h[d.w], 1)] = s.w;
}

__global__ void scat_pm4(const int4* __restrict__ rows, const int4* __restrict__ cols,
                         const float4* __restrict__ vals) {
    int i = blockIdx.x * blockDim.x + threadIdx.x;
    if (i >= NNZn / 4) return;
    int4 r = __ldg(rows + i);
    int4 c = __ldg(cols + i);
    float4 v = __ldg(vals + i);
    g_csr_cv[atomicAdd(&g_cur_p[r.x], 1)] = make_int2(c.x, __float_as_int(v.x));
    g_csr_cv[atomicAdd(&g_cur_p[r.y], 1)] = make_int2(c.y, __float_as_int(v.y));
    g_csr_cv[atomicAdd(&g_cur_p[r.z], 1)] = make_int2(c.z, __float_as_int(v.z));
    g_csr_cv[atomicAdd(&g_cur_p[r.w], 1)] = make_int2(c.w, __float_as_int(v.w));
}

// ---- hop as gather: 4 threads per node, lane l owns one float4 slab. Unroll 8. ----
// Warp = 8 nodes; each row read is 4 coalesced LDG.128 (64B, 1-2 lines).
__global__ void hop_gather(const float* __restrict__ zin, float* __restrict__ zout) {
    int idx = blockIdx.x * blockDim.x + threadIdx.x;
    int node = idx >> 2;
    int l = idx & 3;
    if (node >= Nn) return;
    int e = __ldg(&g_rp_h[node]);
    int end = __ldg(&g_rp_h[node + 1]);
    float4 acc = make_float4(0.f, 0.f, 0.f, 0.f);
    for (; e + 7 < end; e += 8) {
        int s[8];
#pragma unroll
        for (int k = 0; k < 8; k++) s[k] = __ldg(&g_csr_src[e + k]);
        float4 v[8];
#pragma unroll
        for (int k = 0; k < 8; k++)
            v[k] = __ldg((const float4*)(zin + (size_t)s[k] * NF) + l);
#pragma unroll
        for (int k = 0; k < 8; k++) {
            acc.x += v[k].x; acc.y += v[k].y; acc.z += v[k].z; acc.w += v[k].w;
        }
    }
    for (; e < end; e++) {
        int s = __ldg(&g_csr_src[e]);
        float4 v = __ldg((const float4*)(zin + (size_t)s * NF) + l);
        acc.x += v.x; acc.y += v.y; acc.z += v.z; acc.w += v.w;
    }
    ((float4*)(zout + (size_t)node * NF))[l] = acc;
}

// ---- pm_y[n] = sum vals * feat_b[col] over CSR row (4 threads/node, unroll 8) ----
__global__ void pm_gather(const float* __restrict__ fb) {
    int idx = blockIdx.x * blockDim.x + threadIdx.x;
    int node = idx >> 2;
    int l = idx & 3;
    if (node >= Nn) return;
    int e = __ldg(&g_rp_p[node]);
    int end = __ldg(&g_rp_p[node + 1]);
    float4 acc = make_float4(0.f, 0.f, 0.f, 0.f);
    for (; e + 7 < end; e += 8) {
        int2 cv[8];
#pragma unroll
        for (int k = 0; k < 8; k++) cv[k] = __ldg(&g_csr_cv[e + k]);
        float4 v[8];
#pragma unroll
        for (int k = 0; k < 8; k++)
            v[k] = __ldg((const float4*)(fb + (size_t)cv[k].x * NF) + l);
#pragma unroll
        for (int k = 0; k < 8; k++) {
            float w = __int_as_float(cv[k].y);
            acc.x += v[k].x * w; acc.y += v[k].y * w;
            acc.z += v[k].z * w; acc.w += v[k].w * w;
        }
    }
    for (; e < end; e++) {
        int2 cv = __ldg(&g_csr_cv[e]);
        float4 v = __ldg((const float4*)(fb + (size_t)cv.x * NF) + l);
        float w = __int_as_float(cv.y);
        acc.x += v.x * w; acc.y += v.y * w; acc.z += v.z * w; acc.w += v.w * w;
    }
    ((float4*)(g_pmy + (size_t)node * NF))[l] = acc;
}

// ---- fused projection + relu + BN-stat accumulation ----
__global__ void final_kernel(const float* __restrict__ fa,
                             const float* __restrict__ deg,
                             const float* __restrict__ Wprev,
                             const float* __restrict__ bprev,
                             const float* __restrict__ Wdeg,
                             const float* __restrict__ bdeg,
                             const float* __restrict__ Wrad,
                             const float* __restrict__ brad,
                             const float* __restrict__ Wfuse,
                             const float* __restrict__ bfuse,
                             const float* __restrict__ z1,
                             const float* __restrict__ z2,
                             const float* __restrict__ z4,
                             const float* __restrict__ pmy,
                             float* __restrict__ out) {
    __shared__ float sW[1536];
    __shared__ float sB[16];
    __shared__ float sS[32];
    int t = threadIdx.x;
    for (int i = t; i < 256; i += blockDim.x) {
        sW[i] = Wprev[i];
        sW[256 + i] = Wdeg[i];
        sW[1280 + i] = Wfuse[i];
    }
    for (int i = t; i < 768; i += blockDim.x) sW[512 + i] = Wrad[i];
    if (t < 16)
        sB[t] = bprev[t] + bdeg[t] + brad[t] + brad[16 + t] + brad[32 + t] + bfuse[t];
    if (t < 32) sS[t] = 0.f;
    __syncthreads();

    int i = blockIdx.x * blockDim.x + t;
    bool valid = (i < Nn);

    float res[16];
#pragma unroll
    for (int j = 0; j < 16; j++) res[j] = valid ? sB[j] : 0.f;

    if (valid) {
        float in[16];
        const float4* p = (const float4*)(fa + (size_t)i * NF);
        *(float4*)(in + 0)  = p[0];
        *(float4*)(in + 4)  = p[1];
        *(float4*)(in + 8)  = p[2];
        *(float4*)(in + 12) = p[3];
        float dg = deg[i];
#pragma unroll
        for (int k = 0; k < 16; k++) {
            float xv = in[k];
            float xd = xv * dg;
#pragma unroll
            for (int j = 0; j < 16; j++)
                res[j] += xv * sW[k * 16 + j] + xd * sW[256 + k * 16 + j];
        }
        p = (const float4*)(z1 + (size_t)i * NF);
        *(float4*)(in + 0) = p[0]; *(float4*)(in + 4) = p[1];
        *(float4*)(in + 8) = p[2]; *(float4*)(in + 12) = p[3];
#pragma unroll
        for (int k = 0; k < 16; k++) {
            float xv = in[k];
#pragma unroll
            for (int j = 0; j < 16; j++) res[j] += xv * sW[512 + k * 16 + j];
        }
        p = (const float4*)(z2 + (size_t)i * NF);
        *(float4*)(in + 0) = p[0]; *(float4*)(in + 4) = p[1];
        *(float4*)(in + 8) = p[2]; *(float4*)(in + 12) = p[3];
#pragma unroll
        for (int k = 0; k < 16; k++) {
            float xv = in[k];
#pragma unroll
            for (int j = 0; j < 16; j++) res[j] += xv * sW[768 + k * 16 + j];
        }
        p = (const float4*)(z4 + (size_t)i * NF);
        *(float4*)(in + 0) = p[0]; *(float4*)(in + 4) = p[1];
        *(float4*)(in + 8) = p[2]; *(float4*)(in + 12) = p[3];
#pragma unroll
        for (int k = 0; k < 16; k++) {
            float xv = in[k];
#pragma unroll
            for (int j = 0; j < 16; j++) res[j] += xv * sW[1024 + k * 16 + j];
        }
        p = (const float4*)(pmy + (size_t)i * NF);
        *(float4*)(in + 0) = p[0]; *(float4*)(in + 4) = p[1];
        *(float4*)(in + 8) = p[2]; *(float4*)(in + 12) = p[3];
#pragma unroll
        for (int k = 0; k < 16; k++) {
            float xv = in[k];
#pragma unroll
            for (int j = 0; j < 16; j++) res[j] += xv * sW[1280 + k * 16 + j];
        }
#pragma unroll
        for (int j = 8; j < 16; j++) res[j] = fmaxf(res[j], 0.f);
        float4* o = (float4*)(out + (size_t)i * NF);
        o[0] = make_float4(res[0], res[1], res[2], res[3]);
        o[1] = make_float4(res[4], res[5], res[6], res[7]);
        o[2] = make_float4(res[8], res[9], res[10], res[11]);
        o[3] = make_float4(res[12], res[13], res[14], res[15]);
    }

    unsigned lane = t & 31u;
#pragma unroll
    for (int j = 0; j < 16; j++) {
        float s = res[j];
        float q = res[j] * res[j];
#pragma unroll
        for (int o = 16; o > 0; o >>= 1) {
            s += __shfl_xor_sync(0xffffffffu, s, o);
            q += __shfl_xor_sync(0xffffffffu, q, o);
        }
        if (lane == 0) {
            atomicAdd(&sS[j], s);
            atomicAdd(&sS[16 + j], q);
        }
    }
    __syncthreads();
    if (t < 32) atomicAdd(&g_stats[t], sS[t]);
}

// ---- apply batchnorm in place ----
__global__ void bn_kernel(float* __restrict__ out,
                          const float* __restrict__ gamma,
                          const float* __restrict__ beta) {
    __shared__ float sc[16], sh[16];
    if (threadIdx.x < 16) {
        int j = threadIdx.x;
        const float inv = 1.f / (float)Nn;
        float m = g_stats[j] * inv;
        float var = g_stats[16 + j] * inv - m * m;
        float s = rsqrtf(var + 1e-5f) * gamma[j];
        sc[j] = s;
        sh[j] = beta[j] - m * s;
    }
    __syncthreads();
    int tid = blockIdx.x * blockDim.x + threadIdx.x;
    int stride = gridDim.x * blockDim.x;
    const int n4 = Nn * 4;
    float4* o4 = (float4*)out;
    for (int i = tid; i < n4; i += stride) {
        int cb = (i & 3) * 4;
        float4 v = o4[i];
        v.x = v.x * sc[cb + 0] + sh[cb + 0];
        v.y = v.y * sc[cb + 1] + sh[cb + 1];
        v.z = v.z * sc[cb + 2] + sh[cb + 2];
        v.w = v.w * sc[cb + 3] + sh[cb + 3];
        o4[i] = v;
    }
}

extern "C" void kernel_launch(void* const* d_in, const int* in_sizes, int n_in,
                              void* d_out, int out_size) {
    const float* feat_a  = (const float*)d_in[0];
    const float* feat_b  = (const float*)d_in[1];
    const float* deg     = (const float*)d_in[2];
    const float* pm_vals = (const float*)d_in[3];
    const float* W_prev  = (const float*)d_in[4];
    const float* b_prev  = (const float*)d_in[5];
    const float* W_deg   = (const float*)d_in[6];
    const float* b_deg   = (const float*)d_in[7];
    const float* W_rad   = (const float*)d_in[8];
    const float* b_rad   = (const float*)d_in[9];
    const float* W_fuse  = (const float*)d_in[10];
    const float* b_fuse  = (const float*)d_in[11];
    const float* bn_g    = (const float*)d_in[12];
    const float* bn_b    = (const float*)d_in[13];
    const int*   src     = (const int*)d_in[14];
    const int*   dst     = (const int*)d_in[15];
    const int*   pm_rows = (const int*)d_in[16];
    const int*   pm_cols = (const int*)d_in[17];
    float* out = (float*)d_out;

    float *z1, *z2, *zT, *z4, *pmy;
    int *cnt_h, *cnt_p, *rp_h, *rp_p, *cur_h, *cur_p, *bs_h, *bs_p;
    cudaGetSymbolAddress((void**)&z1, g_z1);
    cudaGetSymbolAddress((void**)&z2, g_z2);
    cudaGetSymbolAddress((void**)&zT, g_zT);
    cudaGetSymbolAddress((void**)&z4, g_z4);
    cudaGetSymbolAddress((void**)&pmy, g_pmy);
    cudaGetSymbolAddress((void**)&cnt_h, g_cnt_h);
    cudaGetSymbolAddress((void**)&cnt_p, g_cnt_p);
    cudaGetSymbolAddress((void**)&rp_h, g_rp_h);
    cudaGetSymbolAddress((void**)&rp_p, g_rp_p);
    cudaGetSymbolAddress((void**)&cur_h, g_cur_h);
    cudaGetSymbolAddress((void**)&cur_p, g_cur_p);
    cudaGetSymbolAddress((void**)&bs_h, g_bsum_h);
    cudaGetSymbolAddress((void**)&bs_p, g_bsum_p);

    // Lazily-created side stream + events (host-side infra; device work is
    // identical every call). Fall back to single-stream if creation fails.
    static cudaStream_t s2 = 0;
    static cudaEvent_t ev_fork = 0, ev_join = 0;
    static int infra_ok = -1;
    if (infra_ok < 0) {
        infra_ok = 1;
        if (cudaStreamCreateWithFlags(&s2, cudaStreamNonBlocking) != cudaSuccess) infra_ok = 0;
        if (infra_ok && cudaEventCreateWithFlags(&ev_fork, cudaEventDisableTiming) != cudaSuccess) infra_ok = 0;
        if (infra_ok && cudaEventCreateWithFlags(&ev_join, cudaEventDisableTiming) != cudaSuccess) infra_ok = 0;
    }
    cudaStream_t sp = infra_ok ? s2 : 0;   // pm-path stream

    const int TB = 256;
    const int GG = (Nn * 4 + TB - 1) / TB;   // 4 threads per node

    if (infra_ok) {
        cudaEventRecord(ev_fork, 0);
        cudaStreamWaitEvent(sp, ev_fork, 0);
    }

    // ---- pm path (stream sp): CSR build + gather ----
    zero_pm_kernel<<<256, TB, 0, sp>>>();
    hist4_kernel<<<(NNZn / 4 + TB - 1) / TB, TB, 0, sp>>>((const int4*)pm_rows, NNZn / 4, cnt_p);
    scan_reduce<<<NBLK, SCAN_C, 0, sp>>>(cnt_p, bs_p);
    scan_bsums<<<1, 256, 0, sp>>>(bs_p);
    scan_final<<<NBLK, SCAN_C, 0, sp>>>(cnt_p, bs_p, rp_p, cur_p, NNZn);
    scat_pm4<<<(NNZn / 4 + TB - 1) / TB, TB, 0, sp>>>(
        (const int4*)pm_rows, (const int4*)pm_cols, (const float4*)pm_vals);
    pm_gather<<<GG, TB, 0, sp>>>(feat_b);
    if (infra_ok) cudaEventRecord(ev_join, sp);

    // ---- hop path (default stream): CSR build + 4 gather hops ----
    zero_hop_kernel<<<256, TB>>>();
    hist4_kernel<<<(Ne / 4 + TB - 1) / TB, TB>>>((const int4*)dst, Ne / 4, cnt_h);
    scan_reduce<<<NBLK, SCAN_C>>>(cnt_h, bs_h);
    scan_bsums<<<1, 256>>>(bs_h);
    scan_final<<<NBLK, SCAN_C>>>(cnt_h, bs_h, rp_h, cur_h, Ne);
    scat_hop4<<<(Ne / 4 + TB - 1) / TB, TB>>>((const int4*)src, (const int4*)dst);
    hop_gather<<<GG, TB>>>(feat_a, z1);
    hop_gather<<<GG, TB>>>(z1, z2);
    hop_gather<<<GG, TB>>>(z2, zT);
    hop_gather<<<GG, TB>>>(zT, z4);

    // join pm path before final
    if (infra_ok) cudaStreamWaitEvent(0, ev_join, 0);

    final_kernel<<<(Nn + TB - 1) / TB, TB>>>(
        feat_a, deg, W_prev, b_prev, W_deg, b_deg, W_rad, b_rad,
        W_fuse, b_fuse, z1, z2, z4, pmy, out);

    bn_kernel<<<1024, TB>>>(out, bn_g, bn_b);
}